// round 14
// baseline (speedup 1.0000x reference)
#include <cuda_runtime.h>
#include <cuda_bf16.h>

// Problem constants
#define BB 32
#define CC 64
#define TT 4096
#define NVEC ((BB * CC * TT) / 4)   // 2,097,152 float4 vectors
#define TVEC (TT / 4)               // 1024 (power of two)

#define GRID 1024
#define BLOCK 256
#define NWARPS (BLOCK / 32)
#define ITERS (NVEC / (GRID * BLOCK))   // exactly 8

__device__ float g_partials[GRID];
__device__ unsigned int g_done_count = 0;   // self-resetting per launch

__device__ __forceinline__ float block_reduce(float x)
{
    __shared__ float swarp[NWARPS];
    #pragma unroll
    for (int off = 16; off > 0; off >>= 1)
        x += __shfl_down_sync(0xFFFFFFFFu, x, off);
    int lane = threadIdx.x & 31;
    int wid  = threadIdx.x >> 5;
    if (lane == 0) swarp[wid] = x;
    __syncthreads();
    if (wid == 0) {
        x = (lane < NWARPS) ? swarp[lane] : 0.0f;
        #pragma unroll
        for (int off = NWARPS / 2; off > 0; off >>= 1)
            x += __shfl_down_sync(0xFFFFFFFFu, x, off);
    }
    return x;  // valid in thread 0
}

__device__ __forceinline__ float wabs4(const float4& p, const float4& t, float w)
{
    return fabsf(p.x - t.x) * w + fabsf(p.y - t.y) * (w - 1.0f)
         + fabsf(p.z - t.z) * (w - 2.0f) + fabsf(p.w - t.w) * (w - 3.0f);
}

// Champion config (R7): regs=32 via minBlocks=8, MLP=4 per chunk, occ~84%.
// Weight w hoisted: stride S = 262144 is a multiple of TVEC=1024, so
// (v0 + i*S) & (TVEC-1) is iteration-invariant.
__global__ __launch_bounds__(BLOCK, 8) void wass_fused_kernel(
    const float4* __restrict__ yp, const float4* __restrict__ yt,
    float* __restrict__ out)
{
    const int v0 = blockIdx.x * BLOCK + threadIdx.x;
    const int S  = GRID * BLOCK;

    const float w = (float)(TT - 4 * (v0 & (TVEC - 1)));

    float acc = 0.0f;

    #pragma unroll
    for (int c = 0; c < ITERS / 2; c++) {
        const int va = v0 + (2 * c + 0) * S;
        const int vb = v0 + (2 * c + 1) * S;

        // 4 loads front-batched before any compute.
        float4 p0 = yp[va];
        float4 t0 = yt[va];
        float4 p1 = yp[vb];
        float4 t1 = yt[vb];

        acc += wabs4(p0, t0, w);
        acc += wabs4(p1, t1, w);
    }

    float bsum = block_reduce(acc);

    __shared__ bool s_is_last;
    if (threadIdx.x == 0) {
        g_partials[blockIdx.x] = bsum;
        __threadfence();                       // partial visible before counting
        unsigned int n = atomicAdd(&g_done_count, 1u);
        s_is_last = (n == GRID - 1);
        if (s_is_last) g_done_count = 0;       // reset for next graph replay
    }
    __syncthreads();

    if (s_is_last) {
        // Deterministic final reduce: fixed order over g_partials.
        float a = 0.0f;
        #pragma unroll 4
        for (int i = threadIdx.x; i < GRID; i += BLOCK)
            a += g_partials[i];
        float total = block_reduce(a);
        if (threadIdx.x == 0) {
            double scaling = 2.0 / ((double)TT * (double)CC * (double)(TT + 1));
            out[0] = (float)((double)total * scaling / (double)BB);
        }
    }
}

extern "C" void kernel_launch(void* const* d_in, const int* in_sizes, int n_in,
                              void* d_out, int out_size)
{
    const float4* yp = reinterpret_cast<const float4*>(d_in[0]);
    const float4* yt = reinterpret_cast<const float4*>(d_in[1]);
    float* out = reinterpret_cast<float*>(d_out);
    wass_fused_kernel<<<GRID, BLOCK>>>(yp, yt, out);
}